// round 9
// baseline (speedup 1.0000x reference)
#include <cuda_runtime.h>
#include <cuda_bf16.h>
#include <math.h>
#include <stdint.h>

#define Bc 4
#define Lc 4096
#define Hc 16
#define Dc 128
#define BHc 64
#define SPLITQ 8
#define KVS 2
#define EPSc 1e-6f

// ---------------- device scratch ----------------
__device__ float g_qpart[BHc * SPLITQ * Dc];
__device__ float g_alpha[BHc * Lc];
__device__ float g_kvpart[(size_t)KVS * BHc * Dc * Dc];
__device__ __nv_bfloat16 g_kv_hi[BHc * Dc * Dc];
__device__ __nv_bfloat16 g_kv_lo[BHc * Dc * Dc];
__device__ float g_ksumpart[KVS * BHc * Dc];
__device__ float g_ksum[BHc * Dc];

// ---------------- helpers ----------------
__device__ __forceinline__ uint32_t smem_u32(const void* p) {
    uint32_t a;
    asm("{ .reg .u64 t; cvta.to.shared.u64 t, %1; cvt.u32.u64 %0, t; }" : "=r"(a) : "l"(p));
    return a;
}
__device__ __forceinline__ void ldsm_x4(uint32_t r[4], uint32_t addr) {
    asm volatile("ldmatrix.sync.aligned.m8n8.x4.shared.b16 {%0,%1,%2,%3}, [%4];"
                 : "=r"(r[0]), "=r"(r[1]), "=r"(r[2]), "=r"(r[3]) : "r"(addr));
}
__device__ __forceinline__ void ldsm_x4_t(uint32_t r[4], uint32_t addr) {
    asm volatile("ldmatrix.sync.aligned.m8n8.x4.trans.shared.b16 {%0,%1,%2,%3}, [%4];"
                 : "=r"(r[0]), "=r"(r[1]), "=r"(r[2]), "=r"(r[3]) : "r"(addr));
}
__device__ __forceinline__ void mma16816(float c[4], const uint32_t a[4], uint32_t b0, uint32_t b1) {
    asm volatile(
        "mma.sync.aligned.m16n8k16.row.col.f32.bf16.bf16.f32 "
        "{%0,%1,%2,%3}, {%4,%5,%6,%7}, {%8,%9}, {%0,%1,%2,%3};"
        : "+f"(c[0]), "+f"(c[1]), "+f"(c[2]), "+f"(c[3])
        : "r"(a[0]), "r"(a[1]), "r"(a[2]), "r"(a[3]), "r"(b0), "r"(b1));
}
__device__ __forceinline__ void split_bf16(float x, __nv_bfloat16& h, __nv_bfloat16& l) {
    h = __float2bfloat16(x);
    l = __float2bfloat16(x - __bfloat162float(h));
}
__device__ __forceinline__ uint32_t pack_bf16(__nv_bfloat16 a, __nv_bfloat16 b) {
    __nv_bfloat162 t;
    t.x = a; t.y = b;
    return *reinterpret_cast<uint32_t*>(&t);
}
__device__ __forceinline__ void split4(float4 v, uint2& hi, uint2& lo) {
    __nv_bfloat16 h0, l0, h1, l1, h2, l2, h3, l3;
    split_bf16(v.x, h0, l0); split_bf16(v.y, h1, l1);
    split_bf16(v.z, h2, l2); split_bf16(v.w, h3, l3);
    hi.x = pack_bf16(h0, h1); hi.y = pack_bf16(h2, h3);
    lo.x = pack_bf16(l0, l1); lo.y = pack_bf16(l2, l3);
}

// ================= K1: partial sum of Q over L =================
__global__ void k1_qpart(const float* __restrict__ Q) {
    int bh = blockIdx.x, s = blockIdx.y, d = threadIdx.x;
    int b = bh >> 4, h = bh & 15;
    int l0 = s * (Lc / SPLITQ);
    const float* p = Q + ((size_t)(b * Lc + l0) * Hc + h) * Dc + d;
    float acc = 0.f;
#pragma unroll 8
    for (int i = 0; i < Lc / SPLITQ; i++) { acc += *p; p += Hc * Dc; }
    g_qpart[(bh * SPLITQ + s) * Dc + d] = acc;
}

// ================= K2: scores (q_global folded in) =================
__global__ void k2_scores(const float* __restrict__ K) {
    __shared__ float qg[Dc];
    int bh = blockIdx.x;
    int b = bh >> 4, h = bh & 15;
    int t = threadIdx.x, warp = t >> 5, lane = t & 31;
    if (t < Dc) {
        float acc = 0.f;
#pragma unroll
        for (int s = 0; s < SPLITQ; s++) acc += g_qpart[(bh * SPLITQ + s) * Dc + t];
        qg[t] = acc * (1.0f / ((float)Lc * sqrtf(2048.0f)));
    }
    __syncthreads();
    float4 q = *(const float4*)&qg[lane * 4];
    int l0 = blockIdx.y * 256 + warp * 32;
#pragma unroll 4
    for (int i = 0; i < 32; i++) {
        int l = l0 + i;
        const float4 kk = *(const float4*)(K + ((size_t)(b * Lc + l) * Hc + h) * Dc + lane * 4);
        float p = q.x * kk.x + q.y * kk.y + q.z * kk.z + q.w * kk.w;
        p += __shfl_xor_sync(0xFFFFFFFFu, p, 16);
        p += __shfl_xor_sync(0xFFFFFFFFu, p, 8);
        p += __shfl_xor_sync(0xFFFFFFFFu, p, 4);
        p += __shfl_xor_sync(0xFFFFFFFFu, p, 2);
        p += __shfl_xor_sync(0xFFFFFFFFu, p, 1);
        if (lane == 0) g_alpha[bh * Lc + l] = p;
    }
}

// ================= K3: softmax * L =================
__global__ void k3_softmax() {
    int bh = blockIdx.x, t = threadIdx.x;
    __shared__ float red[256];
    float v[Lc / 256];
#pragma unroll
    for (int i = 0; i < Lc / 256; i++) v[i] = g_alpha[bh * Lc + t + i * 256];
    float m = -1e30f;
#pragma unroll
    for (int i = 0; i < Lc / 256; i++) m = fmaxf(m, v[i]);
    red[t] = m; __syncthreads();
    for (int s = 128; s > 0; s >>= 1) { if (t < s) red[t] = fmaxf(red[t], red[t + s]); __syncthreads(); }
    m = red[0]; __syncthreads();
    float sum = 0.f;
#pragma unroll
    for (int i = 0; i < Lc / 256; i++) { v[i] = expf(v[i] - m); sum += v[i]; }
    red[t] = sum; __syncthreads();
    for (int s = 128; s > 0; s >>= 1) { if (t < s) red[t] += red[t + s]; __syncthreads(); }
    float scale = (float)Lc / red[0];
#pragma unroll
    for (int i = 0; i < Lc / 256; i++) g_alpha[bh * Lc + t + i * 256] = v[i] * scale;
}

// ================= k4: KVT[e][d] = sum_l V[l][e]*(alpha*phiK)[l][d] =================
// grid (BHc, KVS) = 128 blocks, 512 threads. Warp grid 4x4, warp tile m32 x n32.
// Chunks of 64 l-rows, double-buffered smem, register-staged loads.
// MMA issue order is PASS-MAJOR (hh for all accs, then hl, then lh) so each
// accumulator's RAW chain interleaves with 3 others; per-acc op order unchanged.
#define T_KHI 0
#define T_KLO 16384
#define T_VHI 32768
#define T_VLO 49152
#define K4_BUF 65536
#define K4_KS  131072
#define K4_SMEM (131072 + 8192)

__global__ void __launch_bounds__(512) k4_mma(const float* __restrict__ phiK,
                                              const float* __restrict__ V) {
    extern __shared__ __align__(16) char smem[];
    uint32_t sb = smem_u32(smem);
    int bh = blockIdx.x, s = blockIdx.y;
    int b = bh >> 4, h = bh & 15;
    int t = threadIdx.x, lane = t & 31, w = t >> 5;

    float acc[8][4];   // [((mi*2+ni)*2+half)][4]
#pragma unroll
    for (int i = 0; i < 8; i++)
#pragma unroll
        for (int j = 0; j < 4; j++) acc[i][j] = 0.f;
    float4 ksum4 = make_float4(0.f, 0.f, 0.f, 0.f);

    const int c4 = lane;
    const int NCH = (Lc / KVS) / 64;   // 32

    float4 kvst[4], vvst[4];
    float ast[4];

    auto STAGE = [&](int chunk) {
        int l0 = s * (Lc / KVS) + chunk * 64;
#pragma unroll
        for (int i = 0; i < 4; i++) {
            int lr = w + 16 * i;
            int l = l0 + lr;
            size_t off = ((size_t)(b * Lc + l) * Hc + h) * Dc + c4 * 4;
            ast[i] = g_alpha[bh * Lc + l];
            kvst[i] = *(const float4*)(phiK + off);
            vvst[i] = *(const float4*)(V + off);
        }
    };
    auto CVTST = [&](int buf) {
        uint32_t base = (uint32_t)(buf * K4_BUF);
#pragma unroll
        for (int i = 0; i < 4; i++) {
            int lr = w + 16 * i;
            float a = ast[i];
            float4 kv = kvst[i];
            kv.x *= a; kv.y *= a; kv.z *= a; kv.w *= a;
            ksum4.x += kv.x; ksum4.y += kv.y; ksum4.z += kv.z; ksum4.w += kv.w;
            uint32_t wo = lr * 256 + ((((uint32_t)(c4 >> 1)) ^ (lr & 7)) << 4) + (c4 & 1) * 8;
            uint2 hi, lo;
            split4(kv, hi, lo);
            *(uint2*)(smem + base + T_KHI + wo) = hi;
            *(uint2*)(smem + base + T_KLO + wo) = lo;
            split4(vvst[i], hi, lo);
            *(uint2*)(smem + base + T_VHI + wo) = hi;
            *(uint2*)(smem + base + T_VLO + wo) = lo;
        }
    };

    const int ms = w & 3, nh = w >> 2;   // 4x4 warp grid
    const int matj = lane >> 3, rr = lane & 7;
    auto MMA = [&](int buf) {
        uint32_t base = sb + (uint32_t)(buf * K4_BUF);
#pragma unroll
        for (int ks = 0; ks < 4; ks++) {
            int lb = ks * 16;
            // A (V^T) fragments: 2 m16 tiles, hi+lo
            uint32_t ah[2][4], al[2][4];
            int lA = lb + (matj >> 1) * 8 + rr;
#pragma unroll
            for (int mi = 0; mi < 2; mi++) {
                int mt = ms * 2 + mi;
                uint32_t aoff = lA * 256 + ((((uint32_t)(mt * 2 + (matj & 1))) ^ (lA & 7)) << 4);
                ldsm_x4_t(ah[mi], base + T_VHI + aoff);
                ldsm_x4_t(al[mi], base + T_VLO + aoff);
            }
            int lB = lb + (matj & 1) * 8 + rr;
            uint32_t brow = lB * 256;
#pragma unroll
            for (int ni = 0; ni < 2; ni++) {
                int nt = nh * 2 + ni;
                uint32_t boff = brow + ((((uint32_t)(nt * 2 + (matj >> 1))) ^ (lB & 7)) << 4);
                uint32_t bh4[4], bl4[4];
                ldsm_x4_t(bh4, base + T_KHI + boff);
                ldsm_x4_t(bl4, base + T_KLO + boff);
                int a0 = ni * 2, a1 = 4 + ni * 2;   // acc rows for mi=0,1
                // pass hh (4 independent chains)
                mma16816(acc[a0],     ah[0], bh4[0], bh4[1]);
                mma16816(acc[a0 + 1], ah[0], bh4[2], bh4[3]);
                mma16816(acc[a1],     ah[1], bh4[0], bh4[1]);
                mma16816(acc[a1 + 1], ah[1], bh4[2], bh4[3]);
                // pass hl
                mma16816(acc[a0],     ah[0], bl4[0], bl4[1]);
                mma16816(acc[a0 + 1], ah[0], bl4[2], bl4[3]);
                mma16816(acc[a1],     ah[1], bl4[0], bl4[1]);
                mma16816(acc[a1 + 1], ah[1], bl4[2], bl4[3]);
                // pass lh
                mma16816(acc[a0],     al[0], bh4[0], bh4[1]);
                mma16816(acc[a0 + 1], al[0], bh4[2], bh4[3]);
                mma16816(acc[a1],     al[1], bh4[0], bh4[1]);
                mma16816(acc[a1 + 1], al[1], bh4[2], bh4[3]);
            }
        }
    };

    STAGE(0);
    CVTST(0);
    for (int c = 0; c < NCH; c++) {
        __syncthreads();
        if (c + 1 < NCH) STAGE(c + 1);
        MMA(c & 1);
        if (c + 1 < NCH) CVTST((c + 1) & 1);
    }

    // ---- fused ksum partial (fixed-order, deterministic) ----
    __syncthreads();
    *(float4*)(smem + K4_KS + (w * 128 + c4 * 4) * 4) = ksum4;
    __syncthreads();
    if (t < 128) {
        float sum = 0.f;
        const float* ks_s = (const float*)(smem + K4_KS);
#pragma unroll
        for (int g = 0; g < 16; g++) sum += ks_s[g * 128 + t];
        g_ksumpart[(s * BHc + bh) * Dc + t] = sum;
    }

    // ---- epilogue: write fp32 partials ----
    int r_in = lane >> 2;
    int cc_in = 2 * (lane & 3);
#pragma unroll
    for (int mi = 0; mi < 2; mi++) {
#pragma unroll
        for (int ni = 0; ni < 2; ni++) {
#pragma unroll
            for (int half = 0; half < 2; half++) {
                const float* a = acc[mi * 4 + ni * 2 + half];
                int row = ms * 32 + mi * 16 + r_in;
                int col = nh * 32 + ni * 16 + half * 8 + cc_in;
                float* dst = g_kvpart + (((size_t)s * BHc + bh) * Dc + row) * Dc + col;
                *(float2*)(dst)          = make_float2(a[0], a[1]);
                *(float2*)(dst + 8 * Dc) = make_float2(a[2], a[3]);
            }
        }
    }
}

// ================= k4b: reduce partials + split to bf16 hi/lo (+ ksum reduce folded) =================
__global__ void k4b_reduce() {
    int idx = blockIdx.x * blockDim.x + threadIdx.x;
    if (idx >= BHc * Dc * Dc) return;
    float acc = 0.f;
#pragma unroll
    for (int s = 0; s < KVS; s++) acc += g_kvpart[(size_t)s * (BHc * Dc * Dc) + idx];
    __nv_bfloat16 h, l;
    split_bf16(acc, h, l);
    g_kv_hi[idx] = h;
    g_kv_lo[idx] = l;
    if (idx < BHc * Dc) {
        float ks = 0.f;
#pragma unroll
        for (int s = 0; s < KVS; s++) ks += g_ksumpart[s * (BHc * Dc) + idx];
        g_ksum[idx] = ks;
    }
}

// ================= k5: out[l][e] = (phiQ @ KVT^T) / (phiQ . ksum + eps) =================
// grid (BHc, 2) = 128 blocks, 512 threads. Warp grid 4x4, warp tile m32 x n32.
// 16 l-tiles of 128 per block; B resident; A double-buffered, fill interleaved with MMA.
// Pass-major MMA ordering (same per-acc order as before).
#define K5_TILES 16
#define K5_QHI 0
#define K5_QLO 32768
#define K5_ABUF 65536
#define K5_GHI 131072
#define K5_GLO 163840
#define K5_DEN 196608
#define K5_SMEM (196608 + 1024)

__global__ void __launch_bounds__(512) k5_mma(const float* __restrict__ phiQ,
                                              float* __restrict__ out) {
    extern __shared__ __align__(16) char smem[];
    uint32_t sb = smem_u32(smem);
    int bh = blockIdx.x, lt = blockIdx.y;
    int b = bh >> 4, h = bh & 15;
    int l0 = lt * (128 * K5_TILES);
    int t = threadIdx.x, lane = t & 31, w = t >> 5;
    float* den_s = (float*)(smem + K5_DEN);

    const int c4 = lane;
    float4 ksq = *(const float4*)(g_ksum + bh * Dc + c4 * 4);

    // ---- B fill (once) ----
#pragma unroll
    for (int i = 0; i < 4; i++) {
        int seg = t + i * 512;
        int e = seg >> 4, db = seg & 15;
        size_t goff = ((size_t)bh * Dc + e) * Dc + db * 8;
        uint32_t wo = e * 256 + ((((uint32_t)db) ^ (e & 7)) << 4);
        *(uint4*)(smem + K5_GHI + wo) = *(const uint4*)(g_kv_hi + goff);
        *(uint4*)(smem + K5_GLO + wo) = *(const uint4*)(g_kv_lo + goff);
    }

    auto FILLROW = [&](int buf, int row, float4 q) {
        float part = q.x * ksq.x + q.y * ksq.y + q.z * ksq.z + q.w * ksq.w;
        part += __shfl_xor_sync(0xFFFFFFFFu, part, 16);
        part += __shfl_xor_sync(0xFFFFFFFFu, part, 8);
        part += __shfl_xor_sync(0xFFFFFFFFu, part, 4);
        part += __shfl_xor_sync(0xFFFFFFFFu, part, 2);
        part += __shfl_xor_sync(0xFFFFFFFFu, part, 1);
        if (lane == 0) den_s[buf * 128 + row] = part;
        uint32_t base = (uint32_t)(buf * K5_ABUF);
        uint32_t wo = row * 256 + ((((uint32_t)(c4 >> 1)) ^ (row & 7)) << 4) + (c4 & 1) * 8;
        uint2 hi, lo;
        split4(q, hi, lo);
        *(uint2*)(smem + base + K5_QHI + wo) = hi;
        *(uint2*)(smem + base + K5_QLO + wo) = lo;
    };

    // ---- A fill tile0 -> buf0 ----
#pragma unroll
    for (int i = 0; i < 8; i++) {
        int row = w + 16 * i;
        float4 q = *(const float4*)(phiQ + ((size_t)(b * Lc + l0 + row) * Hc + h) * Dc + c4 * 4);
        FILLROW(0, row, q);
    }
    __syncthreads();

    const int ms = w & 3, nh = w >> 2;   // 4x4 warp grid
    const int matj = lane >> 3, rr = lane & 7;
    float acc[8][4];

    auto MMAKS = [&](int buf, int ks) {
        uint32_t abase = sb + (uint32_t)(buf * K5_ABUF);
        // A fragments: 2 m16 tiles, hi+lo
        uint32_t ah[2][4], al[2][4];
        uint32_t kbA = (uint32_t)(ks * 2 + (matj >> 1));
#pragma unroll
        for (int mi = 0; mi < 2; mi++) {
            int rowA = (ms * 2 + mi) * 16 + (matj & 1) * 8 + rr;
            uint32_t aoff = rowA * 256 + ((kbA ^ (rowA & 7)) << 4);
            ldsm_x4(ah[mi], abase + K5_QHI + aoff);
            ldsm_x4(al[mi], abase + K5_QLO + aoff);
        }
        uint32_t kbB = (uint32_t)(ks * 2 + (matj & 1));
#pragma unroll
        for (int ni = 0; ni < 2; ni++) {
            int nt = nh * 2 + ni;
            int rowB = (nt * 2 + (matj >> 1)) * 8 + rr;
            uint32_t boff = rowB * 256 + ((kbB ^ (rowB & 7)) << 4);
            uint32_t bh4[4], bl4[4];
            ldsm_x4(bh4, sb + K5_GHI + boff);
            ldsm_x4(bl4, sb + K5_GLO + boff);
            int a0 = ni * 2, a1 = 4 + ni * 2;
            // pass hh
            mma16816(acc[a0],     ah[0], bh4[0], bh4[1]);
            mma16816(acc[a0 + 1], ah[0], bh4[2], bh4[3]);
            mma16816(acc[a1],     ah[1], bh4[0], bh4[1]);
            mma16816(acc[a1 + 1], ah[1], bh4[2], bh4[3]);
            // pass hl
            mma16816(acc[a0],     ah[0], bl4[0], bl4[1]);
            mma16816(acc[a0 + 1], ah[0], bl4[2], bl4[3]);
            mma16816(acc[a1],     ah[1], bl4[0], bl4[1]);
            mma16816(acc[a1 + 1], ah[1], bl4[2], bl4[3]);
            // pass lh
            mma16816(acc[a0],     al[0], bh4[0], bh4[1]);
            mma16816(acc[a0 + 1], al[0], bh4[2], bh4[3]);
            mma16816(acc[a1],     al[1], bh4[0], bh4[1]);
            mma16816(acc[a1 + 1], al[1], bh4[2], bh4[3]);
        }
    };

    for (int tile = 0; tile < K5_TILES; tile++) {
        int buf = tile & 1, nbuf = buf ^ 1;
#pragma unroll
        for (int i = 0; i < 8; i++)
#pragma unroll
            for (int j = 0; j < 4; j++) acc[i][j] = 0.f;

        if (tile < K5_TILES - 1) {
#pragma unroll
            for (int g = 0; g < 8; g++) {
                int row = w + 16 * g;
                float4 qst = *(const float4*)(phiQ +
                    ((size_t)(b * Lc + l0 + (tile + 1) * 128 + row) * Hc + h) * Dc + c4 * 4);
                MMAKS(buf, g);
                FILLROW(nbuf, row, qst);
            }
        } else {
#pragma unroll
            for (int ks = 0; ks < 8; ks++) MMAKS(buf, ks);
        }

        // ---- epilogue ----
        int r_in = lane >> 2;
        int cc_in = 2 * (lane & 3);
        int lb0 = l0 + tile * 128;
#pragma unroll
        for (int mi = 0; mi < 2; mi++) {
            int row = ms * 32 + mi * 16 + r_in;
            float i0 = 1.0f / (den_s[buf * 128 + row] + EPSc);
            float i1 = 1.0f / (den_s[buf * 128 + row + 8] + EPSc);
            float* o0 = out + ((size_t)(b * Lc + lb0 + row) * Hc + h) * Dc;
            float* o1 = o0 + (size_t)8 * Hc * Dc;
#pragma unroll
            for (int ni = 0; ni < 2; ni++) {
#pragma unroll
                for (int half = 0; half < 2; half++) {
                    const float* a = acc[mi * 4 + ni * 2 + half];
                    int col = nh * 32 + ni * 16 + half * 8 + cc_in;
                    *(float2*)(o0 + col) = make_float2(a[0] * i0, a[1] * i0);
                    *(float2*)(o1 + col) = make_float2(a[2] * i1, a[3] * i1);
                }
            }
        }
        if (tile < K5_TILES - 1) __syncthreads();
    }
}

// ================= launcher =================
extern "C" void kernel_launch(void* const* d_in, const int* in_sizes, int n_in,
                              void* d_out, int out_size) {
    const float* Q    = (const float*)d_in[0];
    const float* K    = (const float*)d_in[1];
    const float* V    = (const float*)d_in[2];
    const float* phiQ = (const float*)d_in[3];
    const float* phiK = (const float*)d_in[4];
    float* out = (float*)d_out;

    cudaFuncSetAttribute(k4_mma, cudaFuncAttributeMaxDynamicSharedMemorySize, K4_SMEM);
    cudaFuncSetAttribute(k5_mma, cudaFuncAttributeMaxDynamicSharedMemorySize, K5_SMEM);

    k1_qpart<<<dim3(BHc, SPLITQ), 128>>>(Q);
    k2_scores<<<dim3(BHc, Lc / 256), 256>>>(K);
    k3_softmax<<<BHc, 256>>>();
    k4_mma<<<dim3(BHc, KVS), 512, K4_SMEM>>>(phiK, V);
    k4b_reduce<<<(BHc * Dc * Dc + 255) / 256, 256>>>();
    k5_mma<<<dim3(BHc, 2), 512, K5_SMEM>>>(phiQ, out);
}

// round 10
// speedup vs baseline: 1.0165x; 1.0165x over previous
#include <cuda_runtime.h>
#include <cuda_bf16.h>
#include <math.h>
#include <stdint.h>

#define Bc 4
#define Lc 4096
#define Hc 16
#define Dc 128
#define BHc 64
#define SPLITQ 8
#define KVS 2
#define EPSc 1e-6f

// ---------------- device scratch ----------------
__device__ float g_qpart[BHc * SPLITQ * Dc];
__device__ float g_alpha[BHc * Lc];
__device__ float g_kvpart[(size_t)KVS * BHc * Dc * Dc];
__device__ float g_ksumpart[KVS * BHc * Dc];

// ---------------- helpers ----------------
__device__ __forceinline__ uint32_t smem_u32(const void* p) {
    uint32_t a;
    asm("{ .reg .u64 t; cvta.to.shared.u64 t, %1; cvt.u32.u64 %0, t; }" : "=r"(a) : "l"(p));
    return a;
}
__device__ __forceinline__ void ldsm_x4(uint32_t r[4], uint32_t addr) {
    asm volatile("ldmatrix.sync.aligned.m8n8.x4.shared.b16 {%0,%1,%2,%3}, [%4];"
                 : "=r"(r[0]), "=r"(r[1]), "=r"(r[2]), "=r"(r[3]) : "r"(addr));
}
__device__ __forceinline__ void ldsm_x4_t(uint32_t r[4], uint32_t addr) {
    asm volatile("ldmatrix.sync.aligned.m8n8.x4.trans.shared.b16 {%0,%1,%2,%3}, [%4];"
                 : "=r"(r[0]), "=r"(r[1]), "=r"(r[2]), "=r"(r[3]) : "r"(addr));
}
__device__ __forceinline__ void mma16816(float c[4], const uint32_t a[4], uint32_t b0, uint32_t b1) {
    asm volatile(
        "mma.sync.aligned.m16n8k16.row.col.f32.bf16.bf16.f32 "
        "{%0,%1,%2,%3}, {%4,%5,%6,%7}, {%8,%9}, {%0,%1,%2,%3};"
        : "+f"(c[0]), "+f"(c[1]), "+f"(c[2]), "+f"(c[3])
        : "r"(a[0]), "r"(a[1]), "r"(a[2]), "r"(a[3]), "r"(b0), "r"(b1));
}
__device__ __forceinline__ void split_bf16(float x, __nv_bfloat16& h, __nv_bfloat16& l) {
    h = __float2bfloat16(x);
    l = __float2bfloat16(x - __bfloat162float(h));
}
__device__ __forceinline__ uint32_t pack_bf16(__nv_bfloat16 a, __nv_bfloat16 b) {
    __nv_bfloat162 t;
    t.x = a; t.y = b;
    return *reinterpret_cast<uint32_t*>(&t);
}
__device__ __forceinline__ void split4(float4 v, uint2& hi, uint2& lo) {
    __nv_bfloat16 h0, l0, h1, l1, h2, l2, h3, l3;
    split_bf16(v.x, h0, l0); split_bf16(v.y, h1, l1);
    split_bf16(v.z, h2, l2); split_bf16(v.w, h3, l3);
    hi.x = pack_bf16(h0, h1); hi.y = pack_bf16(h2, h3);
    lo.x = pack_bf16(l0, l1); lo.y = pack_bf16(l2, l3);
}

#define BAR_SYNC(id)   asm volatile("bar.sync %0, 512;"   :: "r"(id) : "memory")
#define BAR_ARRIVE(id) asm volatile("bar.arrive %0, 512;" :: "r"(id) : "memory")

// ================= K1: partial sum of Q over L =================
__global__ void k1_qpart(const float* __restrict__ Q) {
    int bh = blockIdx.x, s = blockIdx.y, d = threadIdx.x;
    int b = bh >> 4, h = bh & 15;
    int l0 = s * (Lc / SPLITQ);
    const float* p = Q + ((size_t)(b * Lc + l0) * Hc + h) * Dc + d;
    float acc = 0.f;
#pragma unroll 8
    for (int i = 0; i < Lc / SPLITQ; i++) { acc += *p; p += Hc * Dc; }
    g_qpart[(bh * SPLITQ + s) * Dc + d] = acc;
}

// ================= K2: scores (q_global folded in) =================
__global__ void k2_scores(const float* __restrict__ K) {
    __shared__ float qg[Dc];
    int bh = blockIdx.x;
    int b = bh >> 4, h = bh & 15;
    int t = threadIdx.x, warp = t >> 5, lane = t & 31;
    if (t < Dc) {
        float acc = 0.f;
#pragma unroll
        for (int s = 0; s < SPLITQ; s++) acc += g_qpart[(bh * SPLITQ + s) * Dc + t];
        qg[t] = acc * (1.0f / ((float)Lc * sqrtf(2048.0f)));
    }
    __syncthreads();
    float4 q = *(const float4*)&qg[lane * 4];
    int l0 = blockIdx.y * 256 + warp * 32;
#pragma unroll 4
    for (int i = 0; i < 32; i++) {
        int l = l0 + i;
        const float4 kk = *(const float4*)(K + ((size_t)(b * Lc + l) * Hc + h) * Dc + lane * 4);
        float p = q.x * kk.x + q.y * kk.y + q.z * kk.z + q.w * kk.w;
        p += __shfl_xor_sync(0xFFFFFFFFu, p, 16);
        p += __shfl_xor_sync(0xFFFFFFFFu, p, 8);
        p += __shfl_xor_sync(0xFFFFFFFFu, p, 4);
        p += __shfl_xor_sync(0xFFFFFFFFu, p, 2);
        p += __shfl_xor_sync(0xFFFFFFFFu, p, 1);
        if (lane == 0) g_alpha[bh * Lc + l] = p;
    }
}

// ================= K3: softmax * L =================
__global__ void k3_softmax() {
    int bh = blockIdx.x, t = threadIdx.x;
    __shared__ float red[256];
    float v[Lc / 256];
#pragma unroll
    for (int i = 0; i < Lc / 256; i++) v[i] = g_alpha[bh * Lc + t + i * 256];
    float m = -1e30f;
#pragma unroll
    for (int i = 0; i < Lc / 256; i++) m = fmaxf(m, v[i]);
    red[t] = m; __syncthreads();
    for (int s = 128; s > 0; s >>= 1) { if (t < s) red[t] = fmaxf(red[t], red[t + s]); __syncthreads(); }
    m = red[0]; __syncthreads();
    float sum = 0.f;
#pragma unroll
    for (int i = 0; i < Lc / 256; i++) { v[i] = expf(v[i] - m); sum += v[i]; }
    red[t] = sum; __syncthreads();
    for (int s = 128; s > 0; s >>= 1) { if (t < s) red[t] += red[t + s]; __syncthreads(); }
    float scale = (float)Lc / red[0];
#pragma unroll
    for (int i = 0; i < Lc / 256; i++) g_alpha[bh * Lc + t + i * 256] = v[i] * scale;
}

// ================= k4: KVT[e][d] = sum_l V[l][e]*(alpha*phiK)[l][d] =================
// grid (BHc, KVS) = 128 blocks, 512 threads, WARP-SPECIALIZED:
//   warps 0-7  = consumers (LDSM + HMMA, m32 x n64 tiles)
//   warps 8-15 = producers (LDG + alpha-scale + bf16 split + STS, + ksum)
// 32-row chunks, 3 buffers, named-barrier FULL/EMPTY handshake.
#define K4_BUFS 3
#define K4_BUFSZ 32768
#define K4_KHI 0
#define K4_KLO 8192
#define K4_VHI 16384
#define K4_VLO 24576
#define K4_KS  98304
#define K4_SMEM (98304 + 4096)

__global__ void __launch_bounds__(512) k4_mma(const float* __restrict__ phiK,
                                              const float* __restrict__ V) {
    extern __shared__ __align__(16) char smem[];
    uint32_t sb = smem_u32(smem);
    int bh = blockIdx.x, s = blockIdx.y;
    int b = bh >> 4, h = bh & 15;
    int t = threadIdx.x, lane = t & 31, w = t >> 5;
    const int NCH = (Lc / KVS) / 32;   // 64

    if (w >= 8) {
        // ---------------- producer ----------------
        int pw = w - 8;
        const int c4 = lane;
        float4 ksum4 = make_float4(0.f, 0.f, 0.f, 0.f);
        for (int c = 0; c < NCH; c++) {
            int buf = c % K4_BUFS;
            int l0 = s * (Lc / KVS) + c * 32;
            float4 kvst[4], vvst[4];
            float ast[4];
#pragma unroll
            for (int i = 0; i < 4; i++) {
                int lr = pw + 8 * i;
                int l = l0 + lr;
                size_t off = ((size_t)(b * Lc + l) * Hc + h) * Dc + c4 * 4;
                ast[i] = g_alpha[bh * Lc + l];
                kvst[i] = *(const float4*)(phiK + off);
                vvst[i] = *(const float4*)(V + off);
            }
            if (c >= K4_BUFS) BAR_SYNC(4 + buf);
            uint32_t base = (uint32_t)(buf * K4_BUFSZ);
#pragma unroll
            for (int i = 0; i < 4; i++) {
                int lr = pw + 8 * i;
                float a = ast[i];
                float4 kv = kvst[i];
                kv.x *= a; kv.y *= a; kv.z *= a; kv.w *= a;
                ksum4.x += kv.x; ksum4.y += kv.y; ksum4.z += kv.z; ksum4.w += kv.w;
                uint32_t wo = lr * 256 + ((((uint32_t)(c4 >> 1)) ^ (lr & 7)) << 4) + (c4 & 1) * 8;
                uint2 hi, lo;
                split4(kv, hi, lo);
                *(uint2*)(smem + base + K4_KHI + wo) = hi;
                *(uint2*)(smem + base + K4_KLO + wo) = lo;
                split4(vvst[i], hi, lo);
                *(uint2*)(smem + base + K4_VHI + wo) = hi;
                *(uint2*)(smem + base + K4_VLO + wo) = lo;
            }
            BAR_ARRIVE(1 + buf);
        }
        *(float4*)(smem + K4_KS + (pw * 128 + lane * 4) * 4) = ksum4;
        __syncthreads();
    } else {
        // ---------------- consumer ----------------
        float acc[16][4];
#pragma unroll
        for (int i = 0; i < 16; i++)
#pragma unroll
            for (int j = 0; j < 4; j++) acc[i][j] = 0.f;
        const int ms = w & 3, nh = w >> 2;
        const int matj = lane >> 3, rr = lane & 7;
        for (int c = 0; c < NCH; c++) {
            int buf = c % K4_BUFS;
            BAR_SYNC(1 + buf);
            uint32_t base = sb + (uint32_t)(buf * K4_BUFSZ);
#pragma unroll
            for (int ks = 0; ks < 2; ks++) {
                int lb = ks * 16;
                int lA = lb + (matj >> 1) * 8 + rr;
                uint32_t ah[2][4], al[2][4];
#pragma unroll
                for (int mi = 0; mi < 2; mi++) {
                    int mt = ms * 2 + mi;
                    uint32_t aoff = lA * 256 + ((((uint32_t)(mt * 2 + (matj & 1))) ^ (lA & 7)) << 4);
                    ldsm_x4_t(ah[mi], base + K4_VHI + aoff);
                    ldsm_x4_t(al[mi], base + K4_VLO + aoff);
                }
                int lB = lb + (matj & 1) * 8 + rr;
                uint32_t brow = lB * 256;
#pragma unroll
                for (int np = 0; np < 4; np++) {
                    int nt = nh * 4 + np;
                    uint32_t boff = brow + ((((uint32_t)(nt * 2 + (matj >> 1))) ^ (lB & 7)) << 4);
                    uint32_t bh4[4], bl4[4];
                    ldsm_x4_t(bh4, base + K4_KHI + boff);
                    ldsm_x4_t(bl4, base + K4_KLO + boff);
                    int a0 = (0 * 4 + np) * 2, a1 = (1 * 4 + np) * 2;
                    // pass hh
                    mma16816(acc[a0],     ah[0], bh4[0], bh4[1]);
                    mma16816(acc[a0 + 1], ah[0], bh4[2], bh4[3]);
                    mma16816(acc[a1],     ah[1], bh4[0], bh4[1]);
                    mma16816(acc[a1 + 1], ah[1], bh4[2], bh4[3]);
                    // pass hl
                    mma16816(acc[a0],     ah[0], bl4[0], bl4[1]);
                    mma16816(acc[a0 + 1], ah[0], bl4[2], bl4[3]);
                    mma16816(acc[a1],     ah[1], bl4[0], bl4[1]);
                    mma16816(acc[a1 + 1], ah[1], bl4[2], bl4[3]);
                    // pass lh
                    mma16816(acc[a0],     al[0], bh4[0], bh4[1]);
                    mma16816(acc[a0 + 1], al[0], bh4[2], bh4[3]);
                    mma16816(acc[a1],     al[1], bh4[0], bh4[1]);
                    mma16816(acc[a1 + 1], al[1], bh4[2], bh4[3]);
                }
            }
            BAR_ARRIVE(4 + buf);
        }
        // epilogue: write fp32 partials
        int r_in = lane >> 2;
        int cc_in = 2 * (lane & 3);
#pragma unroll
        for (int mi = 0; mi < 2; mi++) {
#pragma unroll
            for (int np = 0; np < 4; np++) {
#pragma unroll
                for (int half = 0; half < 2; half++) {
                    const float* a = acc[(mi * 4 + np) * 2 + half];
                    int row = ms * 32 + mi * 16 + r_in;
                    int col = nh * 64 + np * 16 + half * 8 + cc_in;
                    float* dst = g_kvpart + (((size_t)s * BHc + bh) * Dc + row) * Dc + col;
                    *(float2*)(dst)          = make_float2(a[0], a[1]);
                    *(float2*)(dst + 8 * Dc) = make_float2(a[2], a[3]);
                }
            }
        }
        __syncthreads();
        if (t < 128) {
            float sum = 0.f;
            const float* ks_s = (const float*)(smem + K4_KS);
#pragma unroll
            for (int g = 0; g < 8; g++) sum += ks_s[g * 128 + t];
            g_ksumpart[(s * BHc + bh) * Dc + t] = sum;
        }
    }
}

// ================= k5: out[l][e] = (phiQ @ KVT^T) / (phiQ . ksum + eps) =================
// grid (BHc, 2) = 128 blocks, 512 threads, WARP-SPECIALIZED:
//   warps 0-7  = consumers (LDSM + HMMA + epilogue, m32 x n32 tiles over m64 x n128)
//   warps 8-15 = producers (phiQ LDG + split + STS + denominator)
// B (KV) built in-kernel from fp32 partials (k4b eliminated). 32 tiles of 64 rows.
#define K5_BUFS 3
#define K5_BUFSZ 32768
#define K5_QHI 0
#define K5_QLO 16384
#define K5_GHI 98304
#define K5_GLO 131072
#define K5_DEN 163840
#define K5_KS  164608
#define K5_SMEM (164608 + 512)

__global__ void __launch_bounds__(512) k5_mma(const float* __restrict__ phiQ,
                                              float* __restrict__ out) {
    extern __shared__ __align__(16) char smem[];
    uint32_t sb = smem_u32(smem);
    int bh = blockIdx.x, lt = blockIdx.y;
    int b = bh >> 4, h = bh & 15;
    int l0 = lt * 2048;
    int t = threadIdx.x, lane = t & 31, w = t >> 5;
    float* den_s = (float*)(smem + K5_DEN);
    float* ks_s = (float*)(smem + K5_KS);

    // ---- B fill: reduce KVS=2 fp32 partials, split to bf16 hi/lo (all threads) ----
#pragma unroll
    for (int i = 0; i < 8; i++) {
        int seg = t + i * 512;          // 4096 float4 segments
        int e = seg >> 5, dq = seg & 31;
        size_t off = ((size_t)bh * Dc + e) * Dc + dq * 4;
        float4 p0 = *(const float4*)(g_kvpart + off);
        float4 p1 = *(const float4*)(g_kvpart + (size_t)(BHc * Dc) * Dc + off);
        p0.x += p1.x; p0.y += p1.y; p0.z += p1.z; p0.w += p1.w;
        uint2 hi, lo;
        split4(p0, hi, lo);
        uint32_t wo = e * 256 + ((((uint32_t)(dq >> 1)) ^ (e & 7)) << 4) + (dq & 1) * 8;
        *(uint2*)(smem + K5_GHI + wo) = hi;
        *(uint2*)(smem + K5_GLO + wo) = lo;
    }
    if (t < 128) ks_s[t] = g_ksumpart[bh * Dc + t] + g_ksumpart[BHc * Dc + bh * Dc + t];
    __syncthreads();

    const int NT = 32;   // tiles of 64 l-rows

    if (w >= 8) {
        // ---------------- producer ----------------
        int pw = w - 8;
        const int c4 = lane;
        float4 ksq = *(const float4*)&ks_s[c4 * 4];
        for (int tile = 0; tile < NT; tile++) {
            int buf = tile % K5_BUFS;
            int l0t = l0 + tile * 64;
            float4 qst[8];
#pragma unroll
            for (int i = 0; i < 8; i++) {
                int lr = pw + 8 * i;
                qst[i] = *(const float4*)(phiQ + ((size_t)(b * Lc + l0t + lr) * Hc + h) * Dc + c4 * 4);
            }
            if (tile >= K5_BUFS) BAR_SYNC(4 + buf);
            uint32_t base = (uint32_t)(buf * K5_BUFSZ);
#pragma unroll
            for (int i = 0; i < 8; i++) {
                int lr = pw + 8 * i;
                float4 q = qst[i];
                float part = q.x * ksq.x + q.y * ksq.y + q.z * ksq.z + q.w * ksq.w;
                part += __shfl_xor_sync(0xFFFFFFFFu, part, 16);
                part += __shfl_xor_sync(0xFFFFFFFFu, part, 8);
                part += __shfl_xor_sync(0xFFFFFFFFu, part, 4);
                part += __shfl_xor_sync(0xFFFFFFFFu, part, 2);
                part += __shfl_xor_sync(0xFFFFFFFFu, part, 1);
                if (lane == 0) den_s[buf * 64 + lr] = part;
                uint32_t wo = lr * 256 + ((((uint32_t)(c4 >> 1)) ^ (lr & 7)) << 4) + (c4 & 1) * 8;
                uint2 hi, lo;
                split4(q, hi, lo);
                *(uint2*)(smem + base + K5_QHI + wo) = hi;
                *(uint2*)(smem + base + K5_QLO + wo) = lo;
            }
            BAR_ARRIVE(1 + buf);
        }
    } else {
        // ---------------- consumer ----------------
        const int ms = w & 1, nh = w >> 1;
        const int matj = lane >> 3, rr = lane & 7;
        for (int tile = 0; tile < NT; tile++) {
            int buf = tile % K5_BUFS;
            float acc[8][4];
#pragma unroll
            for (int i = 0; i < 8; i++)
#pragma unroll
                for (int j = 0; j < 4; j++) acc[i][j] = 0.f;
            BAR_SYNC(1 + buf);
            uint32_t abase = sb + (uint32_t)(buf * K5_BUFSZ);
#pragma unroll
            for (int ks = 0; ks < 8; ks++) {
                uint32_t kbA = (uint32_t)(ks * 2 + (matj >> 1));
                uint32_t ah[2][4], al[2][4];
#pragma unroll
                for (int mi = 0; mi < 2; mi++) {
                    int rowA = (ms * 2 + mi) * 16 + (matj & 1) * 8 + rr;
                    uint32_t aoff = rowA * 256 + ((kbA ^ (rowA & 7)) << 4);
                    ldsm_x4(ah[mi], abase + K5_QHI + aoff);
                    ldsm_x4(al[mi], abase + K5_QLO + aoff);
                }
                uint32_t kbB = (uint32_t)(ks * 2 + (matj & 1));
#pragma unroll
                for (int np = 0; np < 2; np++) {
                    int nt = nh * 2 + np;
                    int rowB = (nt * 2 + (matj >> 1)) * 8 + rr;
                    uint32_t boff = rowB * 256 + ((kbB ^ (rowB & 7)) << 4);
                    uint32_t bh4[4], bl4[4];
                    ldsm_x4(bh4, sb + K5_GHI + boff);
                    ldsm_x4(bl4, sb + K5_GLO + boff);
                    int a0 = (0 * 2 + np) * 2, a1 = (1 * 2 + np) * 2;
                    // pass hh
                    mma16816(acc[a0],     ah[0], bh4[0], bh4[1]);
                    mma16816(acc[a0 + 1], ah[0], bh4[2], bh4[3]);
                    mma16816(acc[a1],     ah[1], bh4[0], bh4[1]);
                    mma16816(acc[a1 + 1], ah[1], bh4[2], bh4[3]);
                    // pass hl
                    mma16816(acc[a0],     ah[0], bl4[0], bl4[1]);
                    mma16816(acc[a0 + 1], ah[0], bl4[2], bl4[3]);
                    mma16816(acc[a1],     ah[1], bl4[0], bl4[1]);
                    mma16816(acc[a1 + 1], ah[1], bl4[2], bl4[3]);
                    // pass lh
                    mma16816(acc[a0],     al[0], bh4[0], bh4[1]);
                    mma16816(acc[a0 + 1], al[0], bh4[2], bh4[3]);
                    mma16816(acc[a1],     al[1], bh4[0], bh4[1]);
                    mma16816(acc[a1 + 1], al[1], bh4[2], bh4[3]);
                }
            }
            // epilogue (reads den_s before releasing buffer)
            int r_in = lane >> 2;
            int cc_in = 2 * (lane & 3);
            int lb0 = l0 + tile * 64;
#pragma unroll
            for (int mi = 0; mi < 2; mi++) {
                int row = ms * 32 + mi * 16 + r_in;
                float i0 = 1.0f / (den_s[buf * 64 + row] + EPSc);
                float i1 = 1.0f / (den_s[buf * 64 + row + 8] + EPSc);
                float* o0 = out + ((size_t)(b * Lc + lb0 + row) * Hc + h) * Dc;
                float* o1 = o0 + (size_t)8 * Hc * Dc;
#pragma unroll
                for (int np = 0; np < 2; np++) {
#pragma unroll
                    for (int half = 0; half < 2; half++) {
                        const float* a = acc[(mi * 2 + np) * 2 + half];
                        int col = nh * 32 + np * 16 + half * 8 + cc_in;
                        *(float2*)(o0 + col) = make_float2(a[0] * i0, a[1] * i0);
                        *(float2*)(o1 + col) = make_float2(a[2] * i1, a[3] * i1);
                    }
                }
            }
            BAR_ARRIVE(4 + buf);
        }
    }
}

// ================= launcher =================
extern "C" void kernel_launch(void* const* d_in, const int* in_sizes, int n_in,
                              void* d_out, int out_size) {
    const float* Q    = (const float*)d_in[0];
    const float* K    = (const float*)d_in[1];
    const float* V    = (const float*)d_in[2];
    const float* phiQ = (const float*)d_in[3];
    const float* phiK = (const float*)d_in[4];
    float* out = (float*)d_out;

    cudaFuncSetAttribute(k4_mma, cudaFuncAttributeMaxDynamicSharedMemorySize, K4_SMEM);
    cudaFuncSetAttribute(k5_mma, cudaFuncAttributeMaxDynamicSharedMemorySize, K5_SMEM);

    k1_qpart<<<dim3(BHc, SPLITQ), 128>>>(Q);
    k2_scores<<<dim3(BHc, Lc / 256), 256>>>(K);
    k3_softmax<<<BHc, 256>>>();
    k4_mma<<<dim3(BHc, KVS), 512, K4_SMEM>>>(phiK, V);
    k5_mma<<<dim3(BHc, 2), 512, K5_SMEM>>>(phiQ, out);
}

// round 11
// speedup vs baseline: 1.2553x; 1.2349x over previous
#include <cuda_runtime.h>
#include <cuda_bf16.h>
#include <cuda_fp16.h>
#include <math.h>
#include <stdint.h>

#define Bc 4
#define Lc 4096
#define Hc 16
#define Dc 128
#define BHc 64
#define SPLITQ 32
#define KVS 2
#define EPSc 1e-6f

// ---------------- device scratch ----------------
__device__ float g_qpart[Bc * SPLITQ * Hc * Dc];
__device__ float g_alpha[BHc * Lc];
__device__ float g_kvpart[(size_t)KVS * BHc * Dc * Dc];
__device__ float g_ksumpart[KVS * BHc * Dc];

// ---------------- helpers ----------------
__device__ __forceinline__ uint32_t smem_u32(const void* p) {
    uint32_t a;
    asm("{ .reg .u64 t; cvta.to.shared.u64 t, %1; cvt.u32.u64 %0, t; }" : "=r"(a) : "l"(p));
    return a;
}
__device__ __forceinline__ void ldsm_x4(uint32_t r[4], uint32_t addr) {
    asm volatile("ldmatrix.sync.aligned.m8n8.x4.shared.b16 {%0,%1,%2,%3}, [%4];"
                 : "=r"(r[0]), "=r"(r[1]), "=r"(r[2]), "=r"(r[3]) : "r"(addr));
}
__device__ __forceinline__ void ldsm_x4_t(uint32_t r[4], uint32_t addr) {
    asm volatile("ldmatrix.sync.aligned.m8n8.x4.trans.shared.b16 {%0,%1,%2,%3}, [%4];"
                 : "=r"(r[0]), "=r"(r[1]), "=r"(r[2]), "=r"(r[3]) : "r"(addr));
}
__device__ __forceinline__ void mma16816h(float c[4], const uint32_t a[4], uint32_t b0, uint32_t b1) {
    asm volatile(
        "mma.sync.aligned.m16n8k16.row.col.f32.f16.f16.f32 "
        "{%0,%1,%2,%3}, {%4,%5,%6,%7}, {%8,%9}, {%0,%1,%2,%3};"
        : "+f"(c[0]), "+f"(c[1]), "+f"(c[2]), "+f"(c[3])
        : "r"(a[0]), "r"(a[1]), "r"(a[2]), "r"(a[3]), "r"(b0), "r"(b1));
}
__device__ __forceinline__ uint32_t pack_h2(__half a, __half b) {
    __half2 t;
    t.x = a; t.y = b;
    return *reinterpret_cast<uint32_t*>(&t);
}
// fp16 hi/lo split: hi = rn(x), lo = rn(x - hi)
__device__ __forceinline__ void split4h(float4 v, uint2& hi, uint2& lo) {
    __half h0 = __float2half_rn(v.x), h1 = __float2half_rn(v.y);
    __half h2 = __float2half_rn(v.z), h3 = __float2half_rn(v.w);
    __half l0 = __float2half_rn(v.x - __half2float(h0));
    __half l1 = __float2half_rn(v.y - __half2float(h1));
    __half l2 = __float2half_rn(v.z - __half2float(h2));
    __half l3 = __float2half_rn(v.w - __half2float(h3));
    hi.x = pack_h2(h0, h1); hi.y = pack_h2(h2, h3);
    lo.x = pack_h2(l0, l1); lo.y = pack_h2(l2, l3);
}
__device__ __forceinline__ void cvt4h(float4 v, uint2& hi) {
    hi.x = pack_h2(__float2half_rn(v.x), __float2half_rn(v.y));
    hi.y = pack_h2(__float2half_rn(v.z), __float2half_rn(v.w));
}

#define BAR_SYNC(id)   asm volatile("bar.sync %0, 512;"   :: "r"(id) : "memory")
#define BAR_ARRIVE(id) asm volatile("bar.arrive %0, 512;" :: "r"(id) : "memory")

// ================= K1: partial sum of Q over L (contiguous float4 streaming) =================
// grid (Bc, SPLITQ), 512 threads; each block streams 128 contiguous 8KB rows.
__global__ void __launch_bounds__(512) k1_qpart(const float* __restrict__ Q) {
    int b = blockIdx.x, s = blockIdx.y, t = threadIdx.x;
    const float4* p = (const float4*)(Q + ((size_t)b * Lc + s * (Lc / SPLITQ)) * Hc * Dc) + t;
    float4 acc = make_float4(0.f, 0.f, 0.f, 0.f);
#pragma unroll 8
    for (int i = 0; i < Lc / SPLITQ; i++) {
        float4 v = p[(size_t)i * 512];
        acc.x += v.x; acc.y += v.y; acc.z += v.z; acc.w += v.w;
    }
    *(float4*)(g_qpart + (size_t)(b * SPLITQ + s) * (Hc * Dc) + t * 4) = acc;
}

// ================= K2: scores (q_global folded in) =================
__global__ void k2_scores(const float* __restrict__ K) {
    __shared__ float qg[Dc];
    int bh = blockIdx.x;
    int b = bh >> 4, h = bh & 15;
    int t = threadIdx.x, warp = t >> 5, lane = t & 31;
    if (t < Dc) {
        float acc = 0.f;
#pragma unroll
        for (int s = 0; s < SPLITQ; s++)
            acc += g_qpart[((b * SPLITQ + s) * Hc + h) * Dc + t];
        qg[t] = acc * (1.0f / ((float)Lc * sqrtf(2048.0f)));
    }
    __syncthreads();
    float4 q = *(const float4*)&qg[lane * 4];
    int l0 = blockIdx.y * 256 + warp * 32;
#pragma unroll 4
    for (int i = 0; i < 32; i++) {
        int l = l0 + i;
        const float4 kk = *(const float4*)(K + ((size_t)(b * Lc + l) * Hc + h) * Dc + lane * 4);
        float p = q.x * kk.x + q.y * kk.y + q.z * kk.z + q.w * kk.w;
        p += __shfl_xor_sync(0xFFFFFFFFu, p, 16);
        p += __shfl_xor_sync(0xFFFFFFFFu, p, 8);
        p += __shfl_xor_sync(0xFFFFFFFFu, p, 4);
        p += __shfl_xor_sync(0xFFFFFFFFu, p, 2);
        p += __shfl_xor_sync(0xFFFFFFFFu, p, 1);
        if (lane == 0) g_alpha[bh * Lc + l] = p;
    }
}

// ================= K3: softmax * L =================
__global__ void k3_softmax() {
    int bh = blockIdx.x, t = threadIdx.x;
    __shared__ float red[256];
    float v[Lc / 256];
#pragma unroll
    for (int i = 0; i < Lc / 256; i++) v[i] = g_alpha[bh * Lc + t + i * 256];
    float m = -1e30f;
#pragma unroll
    for (int i = 0; i < Lc / 256; i++) m = fmaxf(m, v[i]);
    red[t] = m; __syncthreads();
    for (int s = 128; s > 0; s >>= 1) { if (t < s) red[t] = fmaxf(red[t], red[t + s]); __syncthreads(); }
    m = red[0]; __syncthreads();
    float sum = 0.f;
#pragma unroll
    for (int i = 0; i < Lc / 256; i++) { v[i] = expf(v[i] - m); sum += v[i]; }
    red[t] = sum; __syncthreads();
    for (int s = 128; s > 0; s >>= 1) { if (t < s) red[t] += red[t + s]; __syncthreads(); }
    float scale = (float)Lc / red[0];
#pragma unroll
    for (int i = 0; i < Lc / 256; i++) g_alpha[bh * Lc + t + i * 256] = v[i] * scale;
}

// ================= k4: KVT[e][d] = sum_l V[l][e]*(alpha*phiK)[l][d] =================
// fp16 2-pass: D = V_hi * K_hi + V_hi * K_lo  (V single fp16, aphiK hi+lo)
// grid (BHc, KVS) = 128 blocks, 512 threads, warp grid 4x4 m32 x n32.
// 64-row chunks, double-buffered, register-staged loads.
#define T_KHI 0
#define T_KLO 16384
#define T_VHI 32768
#define K4_BUF 49152
#define K4_KS  98304
#define K4_SMEM (98304 + 8192)

__global__ void __launch_bounds__(512) k4_mma(const float* __restrict__ phiK,
                                              const float* __restrict__ V) {
    extern __shared__ __align__(16) char smem[];
    uint32_t sb = smem_u32(smem);
    int bh = blockIdx.x, s = blockIdx.y;
    int b = bh >> 4, h = bh & 15;
    int t = threadIdx.x, lane = t & 31, w = t >> 5;

    float acc[8][4];   // [mi*4 + ni*2 + half][4]
#pragma unroll
    for (int i = 0; i < 8; i++)
#pragma unroll
        for (int j = 0; j < 4; j++) acc[i][j] = 0.f;
    float4 ksum4 = make_float4(0.f, 0.f, 0.f, 0.f);

    const int c4 = lane;
    const int NCH = (Lc / KVS) / 64;   // 32

    float4 kvst[4], vvst[4];
    float ast[4];

    auto STAGE = [&](int chunk) {
        int l0 = s * (Lc / KVS) + chunk * 64;
#pragma unroll
        for (int i = 0; i < 4; i++) {
            int lr = w + 16 * i;
            int l = l0 + lr;
            size_t off = ((size_t)(b * Lc + l) * Hc + h) * Dc + c4 * 4;
            ast[i] = g_alpha[bh * Lc + l];
            kvst[i] = *(const float4*)(phiK + off);
            vvst[i] = *(const float4*)(V + off);
        }
    };
    auto CVTST = [&](int buf) {
        uint32_t base = (uint32_t)(buf * K4_BUF);
#pragma unroll
        for (int i = 0; i < 4; i++) {
            int lr = w + 16 * i;
            float a = ast[i];
            float4 kv = kvst[i];
            kv.x *= a; kv.y *= a; kv.z *= a; kv.w *= a;
            ksum4.x += kv.x; ksum4.y += kv.y; ksum4.z += kv.z; ksum4.w += kv.w;
            uint32_t wo = lr * 256 + ((((uint32_t)(c4 >> 1)) ^ (lr & 7)) << 4) + (c4 & 1) * 8;
            uint2 hi, lo;
            split4h(kv, hi, lo);
            *(uint2*)(smem + base + T_KHI + wo) = hi;
            *(uint2*)(smem + base + T_KLO + wo) = lo;
            cvt4h(vvst[i], hi);
            *(uint2*)(smem + base + T_VHI + wo) = hi;
        }
    };

    const int ms = w & 3, nh = w >> 2;   // 4x4 warp grid
    const int matj = lane >> 3, rr = lane & 7;
    auto MMA = [&](int buf) {
        uint32_t base = sb + (uint32_t)(buf * K4_BUF);
#pragma unroll
        for (int ks = 0; ks < 4; ks++) {
            int lb = ks * 16;
            uint32_t ah[2][4];
            int lA = lb + (matj >> 1) * 8 + rr;
#pragma unroll
            for (int mi = 0; mi < 2; mi++) {
                int mt = ms * 2 + mi;
                uint32_t aoff = lA * 256 + ((((uint32_t)(mt * 2 + (matj & 1))) ^ (lA & 7)) << 4);
                ldsm_x4_t(ah[mi], base + T_VHI + aoff);
            }
            int lB = lb + (matj & 1) * 8 + rr;
            uint32_t brow = lB * 256;
#pragma unroll
            for (int ni = 0; ni < 2; ni++) {
                int nt = nh * 2 + ni;
                uint32_t boff = brow + ((((uint32_t)(nt * 2 + (matj >> 1))) ^ (lB & 7)) << 4);
                uint32_t bh4[4], bl4[4];
                ldsm_x4_t(bh4, base + T_KHI + boff);
                ldsm_x4_t(bl4, base + T_KLO + boff);
                int a0 = ni * 2, a1 = 4 + ni * 2;
                // pass hh
                mma16816h(acc[a0],     ah[0], bh4[0], bh4[1]);
                mma16816h(acc[a0 + 1], ah[0], bh4[2], bh4[3]);
                mma16816h(acc[a1],     ah[1], bh4[0], bh4[1]);
                mma16816h(acc[a1 + 1], ah[1], bh4[2], bh4[3]);
                // pass hl
                mma16816h(acc[a0],     ah[0], bl4[0], bl4[1]);
                mma16816h(acc[a0 + 1], ah[0], bl4[2], bl4[3]);
                mma16816h(acc[a1],     ah[1], bl4[0], bl4[1]);
                mma16816h(acc[a1 + 1], ah[1], bl4[2], bl4[3]);
            }
        }
    };

    STAGE(0);
    CVTST(0);
    for (int c = 0; c < NCH; c++) {
        __syncthreads();
        if (c + 1 < NCH) STAGE(c + 1);
        MMA(c & 1);
        if (c + 1 < NCH) CVTST((c + 1) & 1);
    }

    // ---- fused ksum partial (fixed-order, deterministic) ----
    __syncthreads();
    *(float4*)(smem + K4_KS + (w * 128 + c4 * 4) * 4) = ksum4;
    __syncthreads();
    if (t < 128) {
        float sum = 0.f;
        const float* ks_s = (const float*)(smem + K4_KS);
#pragma unroll
        for (int g = 0; g < 16; g++) sum += ks_s[g * 128 + t];
        g_ksumpart[(s * BHc + bh) * Dc + t] = sum;
    }

    // ---- epilogue: write fp32 partials ----
    int r_in = lane >> 2;
    int cc_in = 2 * (lane & 3);
#pragma unroll
    for (int mi = 0; mi < 2; mi++) {
#pragma unroll
        for (int ni = 0; ni < 2; ni++) {
#pragma unroll
            for (int half = 0; half < 2; half++) {
                const float* a = acc[mi * 4 + ni * 2 + half];
                int row = ms * 32 + mi * 16 + r_in;
                int col = nh * 32 + ni * 16 + half * 8 + cc_in;
                float* dst = g_kvpart + (((size_t)s * BHc + bh) * Dc + row) * Dc + col;
                *(float2*)(dst)          = make_float2(a[0], a[1]);
                *(float2*)(dst + 8 * Dc) = make_float2(a[2], a[3]);
            }
        }
    }
}

// ================= k5: out[l][e] = (phiQ_hi @ KVT^T) / (phiQ . ksum + eps) =================
// fp16 2-pass: out = Q_hi * G_hi + Q_hi * G_lo. grid (BHc, 2), 512 threads, warp-specialized.
// B (KV) built in-kernel from fp32 partials. 32 tiles of 64 rows, 3 buffers.
#define K5_BUFS 3
#define K5_BUFSZ 16384
#define K5_GHI 49152
#define K5_GLO 81920
#define K5_DEN 114688
#define K5_KS  115456
#define K5_SMEM (115456 + 512)

__global__ void __launch_bounds__(512) k5_mma(const float* __restrict__ phiQ,
                                              float* __restrict__ out) {
    extern __shared__ __align__(16) char smem[];
    uint32_t sb = smem_u32(smem);
    int bh = blockIdx.x, lt = blockIdx.y;
    int b = bh >> 4, h = bh & 15;
    int l0 = lt * 2048;
    int t = threadIdx.x, lane = t & 31, w = t >> 5;
    float* den_s = (float*)(smem + K5_DEN);
    float* ks_s = (float*)(smem + K5_KS);

    // ---- B fill: reduce KVS=2 fp32 partials, split to fp16 hi/lo (all threads) ----
#pragma unroll
    for (int i = 0; i < 8; i++) {
        int seg = t + i * 512;          // 4096 float4 segments
        int e = seg >> 5, dq = seg & 31;
        size_t off = ((size_t)bh * Dc + e) * Dc + dq * 4;
        float4 p0 = *(const float4*)(g_kvpart + off);
        float4 p1 = *(const float4*)(g_kvpart + (size_t)(BHc * Dc) * Dc + off);
        p0.x += p1.x; p0.y += p1.y; p0.z += p1.z; p0.w += p1.w;
        uint2 hi, lo;
        split4h(p0, hi, lo);
        uint32_t wo = e * 256 + ((((uint32_t)(dq >> 1)) ^ (e & 7)) << 4) + (dq & 1) * 8;
        *(uint2*)(smem + K5_GHI + wo) = hi;
        *(uint2*)(smem + K5_GLO + wo) = lo;
    }
    if (t < 128) ks_s[t] = g_ksumpart[bh * Dc + t] + g_ksumpart[BHc * Dc + bh * Dc + t];
    __syncthreads();

    const int NT = 32;   // tiles of 64 l-rows

    if (w >= 8) {
        // ---------------- producer ----------------
        int pw = w - 8;
        const int c4 = lane;
        float4 ksq = *(const float4*)&ks_s[c4 * 4];
        for (int tile = 0; tile < NT; tile++) {
            int buf = tile % K5_BUFS;
            int l0t = l0 + tile * 64;
            float4 qst[8];
#pragma unroll
            for (int i = 0; i < 8; i++) {
                int lr = pw + 8 * i;
                qst[i] = *(const float4*)(phiQ + ((size_t)(b * Lc + l0t + lr) * Hc + h) * Dc + c4 * 4);
            }
            if (tile >= K5_BUFS) BAR_SYNC(4 + buf);
            uint32_t base = (uint32_t)(buf * K5_BUFSZ);
#pragma unroll
            for (int i = 0; i < 8; i++) {
                int lr = pw + 8 * i;
                float4 q = qst[i];
                float part = q.x * ksq.x + q.y * ksq.y + q.z * ksq.z + q.w * ksq.w;
                part += __shfl_xor_sync(0xFFFFFFFFu, part, 16);
                part += __shfl_xor_sync(0xFFFFFFFFu, part, 8);
                part += __shfl_xor_sync(0xFFFFFFFFu, part, 4);
                part += __shfl_xor_sync(0xFFFFFFFFu, part, 2);
                part += __shfl_xor_sync(0xFFFFFFFFu, part, 1);
                if (lane == 0) den_s[buf * 64 + lr] = part;
                uint32_t wo = lr * 256 + ((((uint32_t)(c4 >> 1)) ^ (lr & 7)) << 4) + (c4 & 1) * 8;
                uint2 hi;
                cvt4h(q, hi);
                *(uint2*)(smem + base + wo) = hi;
            }
            BAR_ARRIVE(1 + buf);
        }
    } else {
        // ---------------- consumer ----------------
        const int ms = w & 1, nh = w >> 1;
        const int matj = lane >> 3, rr = lane & 7;
        for (int tile = 0; tile < NT; tile++) {
            int buf = tile % K5_BUFS;
            float acc[8][4];
#pragma unroll
            for (int i = 0; i < 8; i++)
#pragma unroll
                for (int j = 0; j < 4; j++) acc[i][j] = 0.f;
            BAR_SYNC(1 + buf);
            uint32_t abase = sb + (uint32_t)(buf * K5_BUFSZ);
#pragma unroll
            for (int ks = 0; ks < 8; ks++) {
                uint32_t kbA = (uint32_t)(ks * 2 + (matj >> 1));
                uint32_t ah[2][4];
#pragma unroll
                for (int mi = 0; mi < 2; mi++) {
                    int rowA = (ms * 2 + mi) * 16 + (matj & 1) * 8 + rr;
                    uint32_t aoff = rowA * 256 + ((kbA ^ (rowA & 7)) << 4);
                    ldsm_x4(ah[mi], abase + aoff);
                }
                uint32_t kbB = (uint32_t)(ks * 2 + (matj & 1));
#pragma unroll
                for (int np = 0; np < 2; np++) {
                    int nt = nh * 2 + np;
                    int rowB = (nt * 2 + (matj >> 1)) * 8 + rr;
                    uint32_t boff = rowB * 256 + ((kbB ^ (rowB & 7)) << 4);
                    uint32_t bh4[4], bl4[4];
                    ldsm_x4(bh4, sb + K5_GHI + boff);
                    ldsm_x4(bl4, sb + K5_GLO + boff);
                    int a0 = (0 * 2 + np) * 2, a1 = (1 * 2 + np) * 2;
                    // pass hh
                    mma16816h(acc[a0],     ah[0], bh4[0], bh4[1]);
                    mma16816h(acc[a0 + 1], ah[0], bh4[2], bh4[3]);
                    mma16816h(acc[a1],     ah[1], bh4[0], bh4[1]);
                    mma16816h(acc[a1 + 1], ah[1], bh4[2], bh4[3]);
                    // pass hl
                    mma16816h(acc[a0],     ah[0], bl4[0], bl4[1]);
                    mma16816h(acc[a0 + 1], ah[0], bl4[2], bl4[3]);
                    mma16816h(acc[a1],     ah[1], bl4[0], bl4[1]);
                    mma16816h(acc[a1 + 1], ah[1], bl4[2], bl4[3]);
                }
            }
            // epilogue (reads den_s before releasing buffer)
            int r_in = lane >> 2;
            int cc_in = 2 * (lane & 3);
            int lb0 = l0 + tile * 64;
#pragma unroll
            for (int mi = 0; mi < 2; mi++) {
                int row = ms * 32 + mi * 16 + r_in;
                float i0 = 1.0f / (den_s[buf * 64 + row] + EPSc);
                float i1 = 1.0f / (den_s[buf * 64 + row + 8] + EPSc);
                float* o0 = out + ((size_t)(b * Lc + lb0 + row) * Hc + h) * Dc;
                float* o1 = o0 + (size_t)8 * Hc * Dc;
#pragma unroll
                for (int np = 0; np < 2; np++) {
#pragma unroll
                    for (int half = 0; half < 2; half++) {
                        const float* a = acc[(mi * 2 + np) * 2 + half];
                        int col = nh * 32 + np * 16 + half * 8 + cc_in;
                        *(float2*)(o0 + col) = make_float2(a[0] * i0, a[1] * i0);
                        *(float2*)(o1 + col) = make_float2(a[2] * i1, a[3] * i1);
                    }
                }
            }
            BAR_ARRIVE(4 + buf);
        }
    }
}

// ================= launcher =================
extern "C" void kernel_launch(void* const* d_in, const int* in_sizes, int n_in,
                              void* d_out, int out_size) {
    const float* Q    = (const float*)d_in[0];
    const float* K    = (const float*)d_in[1];
    const float* V    = (const float*)d_in[2];
    const float* phiQ = (const float*)d_in[3];
    const float* phiK = (const float*)d_in[4];
    float* out = (float*)d_out;

    cudaFuncSetAttribute(k4_mma, cudaFuncAttributeMaxDynamicSharedMemorySize, K4_SMEM);
    cudaFuncSetAttribute(k5_mma, cudaFuncAttributeMaxDynamicSharedMemorySize, K5_SMEM);

    k1_qpart<<<dim3(Bc, SPLITQ), 512>>>(Q);
    k2_scores<<<dim3(BHc, Lc / 256), 256>>>(K);
    k3_softmax<<<BHc, 256>>>();
    k4_mma<<<dim3(BHc, KVS), 512, K4_SMEM>>>(phiK, V);
    k5_mma<<<dim3(BHc, 2), 512, K5_SMEM>>>(phiQ, out);
}